// round 15
// baseline (speedup 1.0000x reference)
#include <cuda_runtime.h>
#include <cstdint>

#define BB 8
#define SS 1024
#define HH 8
#define DHD 128

// bf16x2-packed scratch, fragment-permuted layouts:
// g_Qb/g_Kb: [b][h][s][64 u32]  (d pairs, per-16 block permuted)
// g_Vtb:     [b][h][d][512 u32] (s pairs, per-16 block permuted)
__device__ uint32_t g_Qb [BB*HH*SS*64];
__device__ uint32_t g_Kb [BB*HH*SS*64];
__device__ uint32_t g_Vtb[BB*HH*DHD*512];

__device__ __forceinline__ uint32_t packbf(float lo, float hi) {
    uint32_t r;
    asm("cvt.rn.bf16x2.f32 %0, %1, %2;" : "=r"(r) : "f"(hi), "f"(lo));
    return r;
}
__device__ __forceinline__ float ex2f(float x) {
    float r;
    asm("ex2.approx.f32 %0, %1;" : "=f"(r) : "f"(x));
    return r;
}
__device__ __forceinline__ uint32_t smem_u32(const void* p) {
    uint32_t a;
    asm("{ .reg .u64 t; cvta.to.shared.u64 t, %1; cvt.u32.u64 %0, t; }" : "=r"(a) : "l"(p));
    return a;
}
// tf32 m16n8k8: operands are raw fp32 bits (HW truncates low mantissa).
__device__ __forceinline__ void mma8(float* d, const uint32_t* a, const uint32_t* b) {
    asm volatile("mma.sync.aligned.m16n8k8.row.col.f32.tf32.tf32.f32 "
        "{%0,%1,%2,%3}, {%4,%5,%6,%7}, {%8,%9}, {%0,%1,%2,%3};"
        : "+f"(d[0]), "+f"(d[1]), "+f"(d[2]), "+f"(d[3])
        : "r"(a[0]), "r"(a[1]), "r"(a[2]), "r"(a[3]), "r"(b[0]), "r"(b[1]));
}
__device__ __forceinline__ void mma16(float* d, const uint32_t* a, uint32_t b0, uint32_t b1) {
    asm volatile("mma.sync.aligned.m16n8k16.row.col.f32.bf16.bf16.f32 "
        "{%0,%1,%2,%3}, {%4,%5,%6,%7}, {%8,%9}, {%0,%1,%2,%3};"
        : "+f"(d[0]), "+f"(d[1]), "+f"(d[2]), "+f"(d[3])
        : "r"(a[0]), "r"(a[1]), "r"(a[2]), "r"(a[3]), "r"(b0), "r"(b1));
}
#define CP_ASYNC16(dst, src) \
    asm volatile("cp.async.cg.shared.global [%0], [%1], 16;" :: "r"(dst), "l"(src) : "memory")
#define CP_COMMIT() asm volatile("cp.async.commit_group;" ::: "memory")
#define CP_WAIT(n)  asm volatile("cp.async.wait_group %0;" :: "n"(n) : "memory")

// ---------------------------------------------------------------------------
// Kernel 1: low-rank projection, ONE projection per 64-row CTA, 256 threads,
// 3 CTAs/SM. Two cp.async groups: (WV+X) before stage A, (WU+b) before B.
// SMEM floats: Xs[8704]@0 | WV/T[4224]@8704 | WU[4608]@12928 | b[128]@17536
// total 17664 floats = 70656 B.
// ---------------------------------------------------------------------------
#define QJ_XS   0
#define QJ_WV   8704
#define QJ_WU   12928
#define QJ_B    17536
#define QJ_FLTS 17664

__global__ __launch_bounds__(256, 3) void qkv_kernel(
    const float* __restrict__ x,
    const float* __restrict__ Uq, const float* __restrict__ Vq, const float* __restrict__ bq,
    const float* __restrict__ Uk, const float* __restrict__ Vk, const float* __restrict__ bk,
    const float* __restrict__ Uv, const float* __restrict__ Vv, const float* __restrict__ bv)
{
    extern __shared__ __align__(16) float sm[];
    float* Xs = sm + QJ_XS;
    uint32_t* Xsu = reinterpret_cast<uint32_t*>(Xs);
    uint32_t* Vwu = reinterpret_cast<uint32_t*>(sm + QJ_WV);
    uint32_t* Tsu = Vwu;                       // T aliases WV after stage A
    float*    Tsf = reinterpret_cast<float*>(Tsu);
    uint32_t* Uwu = reinterpret_cast<uint32_t*>(sm + QJ_WU);
    const float* bsm = sm + QJ_B;

    const uint32_t sb = smem_u32(sm);
    const int tid  = threadIdx.x;
    const int wid  = tid >> 5;
    const int lane = tid & 31;
    const int g4   = lane >> 2;
    const int c4   = lane & 3;

    const int s0 = blockIdx.x * 64;
    const int h  = blockIdx.y / 3;
    const int p  = blockIdx.y - h*3;
    const int b  = blockIdx.z;
    const size_t bh = (size_t)(b*HH + h);

    const float* Ug = (p == 0) ? Uq : (p == 1) ? Uk : Uv;
    const float* Vg = (p == 0) ? Vq : (p == 1) ? Vk : Vv;
    const float* bg = (p == 0) ? bq : (p == 1) ? bk : bv;

    // group 0: WV + X (64 rows)
    {
        const float4* vg = reinterpret_cast<const float4*>(Vg) + h*1024;
        #pragma unroll
        for (int k = 0; k < 4; ++k) {
            int idx = tid + (k << 8);
            int r = idx >> 5, dq = idx & 31;
            CP_ASYNC16(sb + (QJ_WV + (r*33 + dq)*4)*4, vg + r*32 + dq);
        }
        const float4* xg = reinterpret_cast<const float4*>(x);
        #pragma unroll
        for (int k = 0; k < 8; ++k) {
            int idx = tid + (k << 8);
            int r = idx >> 5, dq = idx & 31;
            CP_ASYNC16(sb + (QJ_XS + (r*132 + dq*4))*4,
                       xg + (size_t)(b*SS + s0 + r)*256 + h*32 + dq);
        }
        CP_COMMIT();
    }
    // group 1: WU + bias
    {
        const float4* ug = reinterpret_cast<const float4*>(Ug) + h*1024;
        #pragma unroll
        for (int k = 0; k < 4; ++k) {
            int idx = tid + (k << 8);
            int dI = idx >> 3, rr = idx & 7;
            CP_ASYNC16(sb + (QJ_WU + (dI*9 + rr)*4)*4, ug + dI*8 + rr);
        }
        if (tid < 32)
            CP_ASYNC16(sb + (QJ_B + tid*4)*4,
                       reinterpret_cast<const float4*>(bg) + h*32 + tid);
        CP_COMMIT();
    }

    CP_WAIT(1);
    __syncthreads();

    // ---- stage A: T[64,32], warp = 16 rows x 16 cols (4x2 warp grid) ----
    {
        const int r0 = (wid >> 1)*16 + g4;
        const int wnA = wid & 1;
        float Tacc[2][4];
        #pragma unroll
        for (int nt = 0; nt < 2; ++nt)
            #pragma unroll
            for (int e = 0; e < 4; ++e) Tacc[nt][e] = 0.f;

        #pragma unroll
        for (int ks = 0; ks < 16; ++ks) {
            int kc = ks*8 + c4;
            uint32_t a[4];
            a[0] = Xsu[r0*132 + kc];
            a[1] = Xsu[(r0+8)*132 + kc];
            a[2] = Xsu[r0*132 + kc + 4];
            a[3] = Xsu[(r0+8)*132 + kc + 4];
            #pragma unroll
            for (int nt = 0; nt < 2; ++nt) {
                int n = wnA*16 + nt*8 + g4;
                uint32_t bfr[2] = { Vwu[n*132 + kc], Vwu[n*132 + kc + 4] };
                mma8(Tacc[nt], a, bfr);
            }
        }
        __syncthreads();   // stage-A reads of WV done before T overwrites it

        #pragma unroll
        for (int nt = 0; nt < 2; ++nt) {
            int c = wnA*16 + nt*8 + 2*c4;
            *reinterpret_cast<float2*>(&Tsf[r0*36 + c]) =
                make_float2(Tacc[nt][0], Tacc[nt][1]);
            *reinterpret_cast<float2*>(&Tsf[(r0+8)*36 + c]) =
                make_float2(Tacc[nt][2], Tacc[nt][3]);
        }
    }
    CP_WAIT(0);
    __syncthreads();

    // ---- stage B: Y[64,128] = T @ Uw^T, warp grid 4x2 (16 rows x 64 cols) ----
    const int wr = wid >> 1, wc = wid & 1;
    const int rb = wr*16 + g4;
    float Y[8][4];
    #pragma unroll
    for (int nt = 0; nt < 8; ++nt)
        #pragma unroll
        for (int e = 0; e < 4; ++e) Y[nt][e] = 0.f;

    #pragma unroll
    for (int ks2 = 0; ks2 < 4; ++ks2) {
        int kk = ks2*8 + c4;
        uint32_t a[4];
        a[0] = Tsu[rb*36 + kk];
        a[1] = Tsu[(rb+8)*36 + kk];
        a[2] = Tsu[rb*36 + kk + 4];
        a[3] = Tsu[(rb+8)*36 + kk + 4];
        #pragma unroll
        for (int nt = 0; nt < 8; ++nt) {
            int n = wc*64 + nt*8 + g4;
            uint32_t bfr[2] = { Uwu[n*36 + kk], Uwu[n*36 + kk + 4] };
            mma8(Y[nt], a, bfr);
        }
    }

    if (p < 2) {
        const float scl = (p == 0) ? 0.12751744610657804f : 1.0f;
        uint32_t* og = (p == 0 ? g_Qb : g_Kb) + (bh*SS + s0)*64;
        #pragma unroll
        for (int nt = 0; nt < 8; ++nt) {
            int c = wc*64 + nt*8 + 2*c4;
            int ks = wc*4 + (nt >> 1);
            int dest = (ks >> 1)*16 + c4*4 + (ks & 1)*2 + (nt & 1);
            float bv0 = bsm[c], bv1 = bsm[c+1];
            og[(size_t)rb*64 + dest] =
                packbf((Y[nt][0]+bv0)*scl, (Y[nt][1]+bv1)*scl);
            og[(size_t)(rb+8)*64 + dest] =
                packbf((Y[nt][2]+bv0)*scl, (Y[nt][3]+bv1)*scl);
        }
    } else {
        // V: transpose via Xs as [d][64 s] stride 68 (X is dead)
        __syncthreads();
        #pragma unroll
        for (int nt = 0; nt < 8; ++nt) {
            int c = wc*64 + nt*8 + 2*c4;
            float bv0 = bsm[c], bv1 = bsm[c+1];
            Xs[c*68 + rb]         = Y[nt][0]+bv0;
            Xs[(c+1)*68 + rb]     = Y[nt][1]+bv1;
            Xs[c*68 + rb + 8]     = Y[nt][2]+bv0;
            Xs[(c+1)*68 + rb + 8] = Y[nt][3]+bv1;
        }
        __syncthreads();
        uint32_t* vt = g_Vtb + bh*DHD*512;
        #pragma unroll
        for (int k = 0; k < 16; ++k) {
            int idx = tid + (k << 8);
            int d = idx >> 5, gp = idx & 31;
            float2 v = *reinterpret_cast<const float2*>(&Xs[d*68 + 2*gp]);
            int tile = gp >> 4, j = gp & 15;
            int s = j & 7, ks2 = j >> 3;
            int dest = (s & 3)*4 + ks2*2 + (s >> 2);
            vt[(size_t)d*512 + blockIdx.x*32 + tile*16 + dest] = packbf(v.x, v.y);
        }
    }
}

// ---------------------------------------------------------------------------
// Kernel 2: flash attention, bf16 m16n8k16, warp-local P, 64-row CTAs,
// 128 threads, 4 CTAs/SM. TWO buffers, unroll-by-2, all smem offsets
// constant (no div/mod, no rotating pointers -> no register growth).
// SMEM u32: K0@0 K1@2560 | V0@5120 V1@7168   (36864 B)
// ---------------------------------------------------------------------------
#define K_STRIDE 2560
#define V_BASE   5120
#define V_STRIDE 2048
#define AT_U32   9216

__device__ __forceinline__ void prefetch_tile(
    uint32_t sb, int tid, const uint32_t* Kg, const uint32_t* Vg,
    int t, uint32_t koff, uint32_t voff)
{
    #pragma unroll
    for (int k = 0; k < 4; ++k) {
        int idx = tid + (k << 7);
        int r = idx >> 4, ch = idx & 15;
        CP_ASYNC16(sb + (koff + r*80 + ch*4)*4, Kg + ((size_t)t*32 + r)*64 + ch*4);
    }
    #pragma unroll
    for (int k = 0; k < 4; ++k) {
        int idx = tid + (k << 7);
        int r = idx >> 2, ch = idx & 3;
        CP_ASYNC16(sb + (voff + r*16 + ch*4)*4, Vg + (size_t)r*512 + t*16 + ch*4);
    }
    CP_COMMIT();
}

__device__ __forceinline__ void attn_tile(
    const uint32_t* Ks, const uint32_t* Vs,
    const uint32_t (&qa)[8][4], float (&O)[16][4],
    float& lsum0, float& lsum1, int g4, int c4)
{
    // ---- S = Q K^T over 32 keys ----
    float S[4][4];
    #pragma unroll
    for (int nt = 0; nt < 4; ++nt) {
        #pragma unroll
        for (int e = 0; e < 4; ++e) S[nt][e] = 0.f;
        const uint32_t* krow = Ks + (nt*8 + g4)*80 + c4*4;
        #pragma unroll
        for (int w = 0; w < 4; ++w) {
            uint4 kv = *reinterpret_cast<const uint4*>(krow + w*16);
            mma16(S[nt], qa[2*w],     kv.x, kv.y);
            mma16(S[nt], qa[2*w + 1], kv.z, kv.w);
        }
    }

    // ---- P = ex2(S) in registers; repack C->A (bf16) ----
    uint32_t ap[2][4];
    #pragma unroll
    for (int nt = 0; nt < 4; ++nt) {
        float p0 = ex2f(S[nt][0]);
        float p1 = ex2f(S[nt][1]);
        float p2 = ex2f(S[nt][2]);
        float p3 = ex2f(S[nt][3]);
        lsum0 += p0 + p1;
        lsum1 += p2 + p3;
        ap[nt >> 1][(nt & 1) ? 2 : 0] = packbf(p0, p1);
        ap[nt >> 1][(nt & 1) ? 3 : 1] = packbf(p2, p3);
    }

    // ---- O += P V over all 128 d ----
    #pragma unroll
    for (int nt = 0; nt < 16; ++nt) {
        uint4 vv = *reinterpret_cast<const uint4*>(Vs + (nt*8 + g4)*16 + c4*4);
        mma16(O[nt], ap[0], vv.x, vv.y);
        mma16(O[nt], ap[1], vv.z, vv.w);
    }
}

__global__ __launch_bounds__(128, 4) void attn_kernel(float* __restrict__ out)
{
    extern __shared__ __align__(16) uint32_t smu[];
    const uint32_t sb = smem_u32(smu);

    const int tid  = threadIdx.x;
    const int wid  = tid >> 5;
    const int lane = tid & 31;
    const int g4   = lane >> 2;
    const int c4   = lane & 3;

    const int qt = blockIdx.x;           // 64-row tile
    const int h  = blockIdx.y;
    const int b  = blockIdx.z;
    const size_t bh = (size_t)(b*HH + h);

    const uint32_t* Kg = g_Kb + bh*SS*64;
    const uint32_t* Vg = g_Vtb + bh*DHD*512;

    // preload tile 0 -> buffers 0
    prefetch_tile(sb, tid, Kg, Vg, 0, 0, V_BASE);

    // Q fragments in registers (rows qt*64 + wid*16 + g4 / +8)
    uint32_t qa[8][4];
    {
        const uint32_t* q0 = g_Qb + (bh*SS + (size_t)qt*64 + wid*16 + g4)*64;
        #pragma unroll
        for (int ks = 0; ks < 8; ++ks) {
            int col = (ks >> 1)*16 + c4*4 + (ks & 1)*2;
            uint2 lo = *reinterpret_cast<const uint2*>(q0 + col);
            uint2 hi = *reinterpret_cast<const uint2*>(q0 + 8*64 + col);
            qa[ks][0] = lo.x; qa[ks][2] = lo.y;
            qa[ks][1] = hi.x; qa[ks][3] = hi.y;
        }
    }

    float O[16][4];
    #pragma unroll
    for (int nt = 0; nt < 16; ++nt)
        #pragma unroll
        for (int e = 0; e < 4; ++e) O[nt][e] = 0.f;
    float lsum0 = 0.f, lsum1 = 0.f;

    #pragma unroll 1
    for (int i = 0; i < 32; i += 2) {
        // even tile i -> buffer 0
        CP_WAIT(0);
        __syncthreads();
        prefetch_tile(sb, tid, Kg, Vg, i + 1, K_STRIDE, V_BASE + V_STRIDE);
        attn_tile(smu, smu + V_BASE, qa, O, lsum0, lsum1, g4, c4);

        // odd tile i+1 -> buffer 1
        CP_WAIT(0);
        __syncthreads();
        if (i < 30)
            prefetch_tile(sb, tid, Kg, Vg, i + 2, 0, V_BASE);
        attn_tile(smu + K_STRIDE, smu + V_BASE + V_STRIDE, qa, O, lsum0, lsum1, g4, c4);
    }

    // lsum: reduce across c4 lanes (warp owns all keys for its rows)
    lsum0 += __shfl_xor_sync(0xffffffffu, lsum0, 1);
    lsum0 += __shfl_xor_sync(0xffffffffu, lsum0, 2);
    lsum1 += __shfl_xor_sync(0xffffffffu, lsum1, 1);
    lsum1 += __shfl_xor_sync(0xffffffffu, lsum1, 2);
    const float inv0 = 1.f / lsum0;
    const float inv1 = 1.f / lsum1;

    // epilogue: warp writes its 16 rows x 128 d
    {
        float* op0 = out + ((size_t)b*SS + qt*64 + wid*16 + g4)*1024 + h*128 + 2*c4;
        float* op1 = op0 + 8*1024;
        #pragma unroll
        for (int nt = 0; nt < 16; ++nt) {
            *reinterpret_cast<float2*>(op0 + nt*8) =
                make_float2(O[nt][0]*inv0, O[nt][1]*inv0);
            *reinterpret_cast<float2*>(op1 + nt*8) =
                make_float2(O[nt][2]*inv1, O[nt][3]*inv1);
        }
    }
}

// ---------------------------------------------------------------------------
extern "C" void kernel_launch(void* const* d_in, const int* in_sizes, int n_in,
                              void* d_out, int out_size) {
    (void)in_sizes; (void)n_in; (void)out_size;
    const float* x  = (const float*)d_in[0];
    const float* Uq = (const float*)d_in[1];
    const float* Vq = (const float*)d_in[2];
    const float* bq = (const float*)d_in[3];
    const float* Uk = (const float*)d_in[4];
    const float* Vk = (const float*)d_in[5];
    const float* bk = (const float*)d_in[6];
    const float* Uv = (const float*)d_in[7];
    const float* Vv = (const float*)d_in[8];
    const float* bv = (const float*)d_in[9];
    float* out = (float*)d_out;

    const int qkv_smem  = QJ_FLTS * 4;   // 70656 B -> 3 CTAs/SM
    const int attn_smem = AT_U32 * 4;    // 36864 B -> 4 CTAs/SM (reg-limited)
    cudaFuncSetAttribute(qkv_kernel,
                         cudaFuncAttributeMaxDynamicSharedMemorySize, qkv_smem);
    cudaFuncSetAttribute(attn_kernel,
                         cudaFuncAttributeMaxDynamicSharedMemorySize, attn_smem);

    qkv_kernel<<<dim3(SS/64, HH*3, BB), 256, qkv_smem>>>(x, Uq, Vq, bq, Uk, Vk, bk, Uv, Vv, bv);
    attn_kernel<<<dim3(SS/64, HH, BB), 128, attn_smem>>>(out);
}

// round 16
// speedup vs baseline: 1.0220x; 1.0220x over previous
#include <cuda_runtime.h>
#include <cstdint>

#define BB 8
#define SS 1024
#define HH 8
#define DHD 128

// bf16x2-packed scratch, fragment-permuted layouts:
// g_Qb/g_Kb: [b][h][s][64 u32]  (d pairs, per-16 block permuted)
// g_Vtb:     [b][h][d][512 u32] (s pairs, per-16 block permuted)
__device__ uint32_t g_Qb [BB*HH*SS*64];
__device__ uint32_t g_Kb [BB*HH*SS*64];
__device__ uint32_t g_Vtb[BB*HH*DHD*512];

__device__ __forceinline__ uint32_t packbf(float lo, float hi) {
    uint32_t r;
    asm("cvt.rn.bf16x2.f32 %0, %1, %2;" : "=r"(r) : "f"(hi), "f"(lo));
    return r;
}
__device__ __forceinline__ float ex2f(float x) {
    float r;
    asm("ex2.approx.f32 %0, %1;" : "=f"(r) : "f"(x));
    return r;
}
__device__ __forceinline__ uint32_t smem_u32(const void* p) {
    uint32_t a;
    asm("{ .reg .u64 t; cvta.to.shared.u64 t, %1; cvt.u32.u64 %0, t; }" : "=r"(a) : "l"(p));
    return a;
}
// tf32 m16n8k8: operands are raw fp32 bits (HW truncates low mantissa).
__device__ __forceinline__ void mma8(float* d, const uint32_t* a, const uint32_t* b) {
    asm volatile("mma.sync.aligned.m16n8k8.row.col.f32.tf32.tf32.f32 "
        "{%0,%1,%2,%3}, {%4,%5,%6,%7}, {%8,%9}, {%0,%1,%2,%3};"
        : "+f"(d[0]), "+f"(d[1]), "+f"(d[2]), "+f"(d[3])
        : "r"(a[0]), "r"(a[1]), "r"(a[2]), "r"(a[3]), "r"(b[0]), "r"(b[1]));
}
__device__ __forceinline__ void mma16(float* d, const uint32_t* a, uint32_t b0, uint32_t b1) {
    asm volatile("mma.sync.aligned.m16n8k16.row.col.f32.bf16.bf16.f32 "
        "{%0,%1,%2,%3}, {%4,%5,%6,%7}, {%8,%9}, {%0,%1,%2,%3};"
        : "+f"(d[0]), "+f"(d[1]), "+f"(d[2]), "+f"(d[3])
        : "r"(a[0]), "r"(a[1]), "r"(a[2]), "r"(a[3]), "r"(b0), "r"(b1));
}
#define CP_ASYNC16(dst, src) \
    asm volatile("cp.async.cg.shared.global [%0], [%1], 16;" :: "r"(dst), "l"(src) : "memory")
#define CP_COMMIT() asm volatile("cp.async.commit_group;" ::: "memory")
#define CP_WAIT(n)  asm volatile("cp.async.wait_group %0;" :: "n"(n) : "memory")

// ---------------------------------------------------------------------------
// Kernel 1 (exact R14): low-rank projection, ONE projection per 128-row CTA
// (p fastest in y for x-slice L2 reuse), 256 threads, 2 CTAs/SM.
// Two cp.async groups: (WV+X) before stage A, (WU+bias) before stage B.
// SMEM floats: Xs[128*132]@0 | WV/T[4608]@16896 | WU[4608]@21504 | b[128]@26112
// ---------------------------------------------------------------------------
#define QJ_XS   0
#define QJ_WV   16896
#define QJ_WU   21504
#define QJ_B    26112
#define QJ_FLTS 26240

__global__ __launch_bounds__(256, 2) void qkv_kernel(
    const float* __restrict__ x,
    const float* __restrict__ Uq, const float* __restrict__ Vq, const float* __restrict__ bq,
    const float* __restrict__ Uk, const float* __restrict__ Vk, const float* __restrict__ bk,
    const float* __restrict__ Uv, const float* __restrict__ Vv, const float* __restrict__ bv)
{
    extern __shared__ __align__(16) float sm[];
    float* Xs = sm + QJ_XS;
    uint32_t* Xsu = reinterpret_cast<uint32_t*>(Xs);
    uint32_t* Vwu = reinterpret_cast<uint32_t*>(sm + QJ_WV);
    uint32_t* Tsu = Vwu;                       // T aliases WV after stage A
    float*    Tsf = reinterpret_cast<float*>(Tsu);
    uint32_t* Uwu = reinterpret_cast<uint32_t*>(sm + QJ_WU);
    const float* bsm = sm + QJ_B;

    const uint32_t sb = smem_u32(sm);
    const int tid  = threadIdx.x;
    const int wid  = tid >> 5;
    const int lane = tid & 31;
    const int g4   = lane >> 2;
    const int c4   = lane & 3;

    const int s0 = blockIdx.x * 128;
    const int h  = blockIdx.y / 3;
    const int p  = blockIdx.y - h*3;
    const int b  = blockIdx.z;
    const size_t bh = (size_t)(b*HH + h);

    const float* Ug = (p == 0) ? Uq : (p == 1) ? Uk : Uv;
    const float* Vg = (p == 0) ? Vq : (p == 1) ? Vk : Vv;
    const float* bg = (p == 0) ? bq : (p == 1) ? bk : bv;

    // group 0: WV + X  (everything stage A needs)
    {
        const float4* vg = reinterpret_cast<const float4*>(Vg) + h*1024;
        #pragma unroll
        for (int k = 0; k < 4; ++k) {
            int idx = tid + (k << 8);
            int r = idx >> 5, dq = idx & 31;
            CP_ASYNC16(sb + (QJ_WV + (r*33 + dq)*4)*4, vg + r*32 + dq);
        }
        const float4* xg = reinterpret_cast<const float4*>(x);
        #pragma unroll
        for (int k = 0; k < 16; ++k) {
            int idx = tid + (k << 8);
            int r = idx >> 5, dq = idx & 31;
            CP_ASYNC16(sb + (QJ_XS + (r*132 + dq*4))*4,
                       xg + (size_t)(b*SS + s0 + r)*256 + h*32 + dq);
        }
        CP_COMMIT();
    }
    // group 1: WU + bias (needed only by stage B)
    {
        const float4* ug = reinterpret_cast<const float4*>(Ug) + h*1024;
        #pragma unroll
        for (int k = 0; k < 4; ++k) {
            int idx = tid + (k << 8);
            int dI = idx >> 3, rr = idx & 7;
            CP_ASYNC16(sb + (QJ_WU + (dI*9 + rr)*4)*4, ug + dI*8 + rr);
        }
        if (tid < 32)
            CP_ASYNC16(sb + (QJ_B + tid*4)*4,
                       reinterpret_cast<const float4*>(bg) + h*32 + tid);
        CP_COMMIT();
    }

    CP_WAIT(1);
    __syncthreads();

    // ---- stage A: T[128,32], warp = 16 rows x 32 cols ----
    const int r0 = wid*16 + g4;
    float Tacc[4][4];
    #pragma unroll
    for (int nt = 0; nt < 4; ++nt)
        #pragma unroll
        for (int e = 0; e < 4; ++e) Tacc[nt][e] = 0.f;

    #pragma unroll
    for (int ks = 0; ks < 16; ++ks) {
        int kc = ks*8 + c4;
        uint32_t a[4];
        a[0] = Xsu[r0*132 + kc];
        a[1] = Xsu[(r0+8)*132 + kc];
        a[2] = Xsu[r0*132 + kc + 4];
        a[3] = Xsu[(r0+8)*132 + kc + 4];
        #pragma unroll
        for (int nt = 0; nt < 4; ++nt) {
            int n = nt*8 + g4;
            uint32_t bfr[2] = { Vwu[n*132 + kc], Vwu[n*132 + kc + 4] };
            mma8(Tacc[nt], a, bfr);
        }
    }
    __syncthreads();   // all stage-A reads of WV done before T overwrites it

    // write T (raw fp32; tf32 truncation happens inside the MMA)
    #pragma unroll
    for (int nt = 0; nt < 4; ++nt) {
        int c = nt*8 + 2*c4;
        *reinterpret_cast<float2*>(&Tsf[r0*36 + c]) =
            make_float2(Tacc[nt][0], Tacc[nt][1]);
        *reinterpret_cast<float2*>(&Tsf[(r0+8)*36 + c]) =
            make_float2(Tacc[nt][2], Tacc[nt][3]);
    }
    CP_WAIT(0);
    __syncthreads();

    // ---- stage B: Y[128,128] = T @ Uw^T, warp grid 4x2 ----
    const int wr = wid >> 1, wc = wid & 1;
    const int rb = wr*32 + g4;
    float Y[2][8][4];
    #pragma unroll
    for (int mt = 0; mt < 2; ++mt)
        #pragma unroll
        for (int nt = 0; nt < 8; ++nt)
            #pragma unroll
            for (int e = 0; e < 4; ++e) Y[mt][nt][e] = 0.f;

    #pragma unroll
    for (int ks2 = 0; ks2 < 4; ++ks2) {
        int kk = ks2*8 + c4;
        uint32_t a[2][4];
        #pragma unroll
        for (int mt = 0; mt < 2; ++mt) {
            int r = rb + mt*16;
            a[mt][0] = Tsu[r*36 + kk];
            a[mt][1] = Tsu[(r+8)*36 + kk];
            a[mt][2] = Tsu[r*36 + kk + 4];
            a[mt][3] = Tsu[(r+8)*36 + kk + 4];
        }
        #pragma unroll
        for (int nt = 0; nt < 8; ++nt) {
            int n = wc*64 + nt*8 + g4;
            uint32_t bfr[2] = { Uwu[n*36 + kk], Uwu[n*36 + kk + 4] };
            mma8(Y[0][nt], a[0], bfr);
            mma8(Y[1][nt], a[1], bfr);
        }
    }

    if (p < 2) {
        const float scl = (p == 0) ? 0.12751744610657804f : 1.0f;
        uint32_t* og = (p == 0 ? g_Qb : g_Kb) + (bh*SS + s0)*64;
        #pragma unroll
        for (int mt = 0; mt < 2; ++mt) {
            int r = rb + mt*16;
            #pragma unroll
            for (int nt = 0; nt < 8; ++nt) {
                int c = wc*64 + nt*8 + 2*c4;
                int ks = wc*4 + (nt >> 1);
                int dest = (ks >> 1)*16 + c4*4 + (ks & 1)*2 + (nt & 1);
                float bv0 = bsm[c], bv1 = bsm[c+1];
                og[(size_t)r*64 + dest] =
                    packbf((Y[mt][nt][0]+bv0)*scl, (Y[mt][nt][1]+bv1)*scl);
                og[(size_t)(r+8)*64 + dest] =
                    packbf((Y[mt][nt][2]+bv0)*scl, (Y[mt][nt][3]+bv1)*scl);
            }
        }
    } else {
        // V: transpose via Xs (X is dead), then permuted bf16x2 store
        __syncthreads();
        #pragma unroll
        for (int mt = 0; mt < 2; ++mt) {
            int r = rb + mt*16;
            #pragma unroll
            for (int nt = 0; nt < 8; ++nt) {
                int c = wc*64 + nt*8 + 2*c4;
                float bv0 = bsm[c], bv1 = bsm[c+1];
                Xs[c*132 + r]         = Y[mt][nt][0]+bv0;
                Xs[(c+1)*132 + r]     = Y[mt][nt][1]+bv1;
                Xs[c*132 + r + 8]     = Y[mt][nt][2]+bv0;
                Xs[(c+1)*132 + r + 8] = Y[mt][nt][3]+bv1;
            }
        }
        __syncthreads();
        uint32_t* vt = g_Vtb + bh*DHD*512;
        #pragma unroll
        for (int k = 0; k < 32; ++k) {
            int idx = tid + (k << 8);
            int d = idx >> 6, gp = idx & 63;
            float v0 = Xs[d*132 + 2*gp];
            float v1 = Xs[d*132 + 2*gp + 1];
            int tile = gp >> 4, j = gp & 15;
            int s = j & 7, ks2 = j >> 3;
            int dest = (s & 3)*4 + ks2*2 + (s >> 2);
            vt[(size_t)d*512 + blockIdx.x*64 + tile*16 + dest] = packbf(v0, v1);
        }
    }
}

// ---------------------------------------------------------------------------
// Kernel 2: flash attention (R14 structure, loop UNROLLED BY 3 so all buffer
// offsets are compile-time constants: no div/mod, no rotating pointers, no
// persistent state). bf16 m16n8k16, warp-local P, 64-row CTAs, 128 threads,
// 4 CTAs/SM, 3 KV buffers, depth-2 prefetch (wait(1) invariant as R14).
// SMEM u32: K[3][2560]@0 | V[3][2048]@7680   (55296 B -> 4 CTAs/SM)
// ---------------------------------------------------------------------------
#define K_STRIDE 2560
#define V_BASE   7680
#define V_STRIDE 2048
#define AT_U32   13824

__device__ __forceinline__ void prefetch_tile(
    uint32_t sb, int tid, const uint32_t* Kg, const uint32_t* Vg,
    int t, int koff, int voff)
{
    #pragma unroll
    for (int k = 0; k < 4; ++k) {
        int idx = tid + (k << 7);
        int r = idx >> 4, ch = idx & 15;
        CP_ASYNC16(sb + (koff + r*80 + ch*4)*4, Kg + ((size_t)t*32 + r)*64 + ch*4);
    }
    #pragma unroll
    for (int k = 0; k < 4; ++k) {
        int idx = tid + (k << 7);
        int r = idx >> 2, ch = idx & 3;
        CP_ASYNC16(sb + (voff + r*16 + ch*4)*4, Vg + (size_t)r*512 + t*16 + ch*4);
    }
    CP_COMMIT();
}

__device__ __forceinline__ void attn_tile(
    const uint32_t* Ks, const uint32_t* Vs,
    const uint32_t (&qa)[8][4], float (&O)[16][4],
    float& lsum0, float& lsum1, int g4, int c4)
{
    // ---- S = Q K^T over 32 keys ----
    float S[4][4];
    #pragma unroll
    for (int nt = 0; nt < 4; ++nt) {
        #pragma unroll
        for (int e = 0; e < 4; ++e) S[nt][e] = 0.f;
        const uint32_t* krow = Ks + (nt*8 + g4)*80 + c4*4;
        #pragma unroll
        for (int w = 0; w < 4; ++w) {
            uint4 kv = *reinterpret_cast<const uint4*>(krow + w*16);
            mma16(S[nt], qa[2*w],     kv.x, kv.y);
            mma16(S[nt], qa[2*w + 1], kv.z, kv.w);
        }
    }

    // ---- P = ex2(S) in registers; repack C->A (bf16) ----
    uint32_t ap[2][4];
    #pragma unroll
    for (int nt = 0; nt < 4; ++nt) {
        float p0 = ex2f(S[nt][0]);
        float p1 = ex2f(S[nt][1]);
        float p2 = ex2f(S[nt][2]);
        float p3 = ex2f(S[nt][3]);
        lsum0 += p0 + p1;
        lsum1 += p2 + p3;
        ap[nt >> 1][(nt & 1) ? 2 : 0] = packbf(p0, p1);
        ap[nt >> 1][(nt & 1) ? 3 : 1] = packbf(p2, p3);
    }

    // ---- O += P V over all 128 d ----
    #pragma unroll
    for (int nt = 0; nt < 16; ++nt) {
        uint4 vv = *reinterpret_cast<const uint4*>(Vs + (nt*8 + g4)*16 + c4*4);
        mma16(O[nt], ap[0], vv.x, vv.y);
        mma16(O[nt], ap[1], vv.z, vv.w);
    }
}

__global__ __launch_bounds__(128, 4) void attn_kernel(float* __restrict__ out)
{
    extern __shared__ __align__(16) uint32_t smu[];
    const uint32_t sb = smem_u32(smu);

    const int tid  = threadIdx.x;
    const int wid  = tid >> 5;
    const int lane = tid & 31;
    const int g4   = lane >> 2;
    const int c4   = lane & 3;

    const int qt = blockIdx.x;           // 64-row tile
    const int h  = blockIdx.y;
    const int b  = blockIdx.z;
    const size_t bh = (size_t)(b*HH + h);

    const uint32_t* Kg = g_Kb + bh*SS*64;
    const uint32_t* Vg = g_Vtb + bh*DHD*512;

    // prefetch tiles 0,1 into buffers 0,1
    prefetch_tile(sb, tid, Kg, Vg, 0, 0,        V_BASE);
    prefetch_tile(sb, tid, Kg, Vg, 1, K_STRIDE, V_BASE + V_STRIDE);

    // Q fragments in registers (rows qt*64 + wid*16 + g4 / +8)
    uint32_t qa[8][4];
    {
        const uint32_t* q0 = g_Qb + (bh*SS + (size_t)qt*64 + wid*16 + g4)*64;
        #pragma unroll
        for (int ks = 0; ks < 8; ++ks) {
            int col = (ks >> 1)*16 + c4*4 + (ks & 1)*2;
            uint2 lo = *reinterpret_cast<const uint2*>(q0 + col);
            uint2 hi = *reinterpret_cast<const uint2*>(q0 + 8*64 + col);
            qa[ks][0] = lo.x; qa[ks][2] = lo.y;
            qa[ks][1] = hi.x; qa[ks][3] = hi.y;
        }
    }

    float O[16][4];
    #pragma unroll
    for (int nt = 0; nt < 16; ++nt)
        #pragma unroll
        for (int e = 0; e < 4; ++e) O[nt][e] = 0.f;
    float lsum0 = 0.f, lsum1 = 0.f;

    // 30 tiles in unrolled triples (buffer phase is compile-time constant),
    // then 2 tail tiles. Invariant (as R14): at tile i, wait(1) guarantees
    // tile i's group complete (only tile i+1's may pend); the sync frees
    // buffer (i+2)%3, last read at tile i-1.
    #pragma unroll 1
    for (int i = 0; i < 30; i += 3) {
        // tile i -> buf0; prefetch t=i+2 -> buf2
        CP_WAIT(1);
        __syncthreads();
        prefetch_tile(sb, tid, Kg, Vg, i + 2, 2*K_STRIDE, V_BASE + 2*V_STRIDE);
        attn_tile(smu, smu + V_BASE, qa, O, lsum0, lsum1, g4, c4);

        // tile i+1 -> buf1; prefetch t=i+3 -> buf0
        CP_WAIT(1);
        __syncthreads();
        prefetch_tile(sb, tid, Kg, Vg, i + 3, 0, V_BASE);
        attn_tile(smu + K_STRIDE, smu + V_BASE + V_STRIDE, qa, O, lsum0, lsum1, g4, c4);

        // tile i+2 -> buf2; prefetch t=i+4 -> buf1
        CP_WAIT(1);
        __syncthreads();
        prefetch_tile(sb, tid, Kg, Vg, i + 4, K_STRIDE, V_BASE + V_STRIDE);
        attn_tile(smu + 2*K_STRIDE, smu + V_BASE + 2*V_STRIDE, qa, O, lsum0, lsum1, g4, c4);
    }
    // tail: tile 30 (buf0) — t=31 may still be in flight; tile 31 (buf1)
    CP_WAIT(1);
    __syncthreads();
    attn_tile(smu, smu + V_BASE, qa, O, lsum0, lsum1, g4, c4);
    CP_WAIT(0);
    __syncthreads();
    attn_tile(smu + K_STRIDE, smu + V_BASE + V_STRIDE, qa, O, lsum0, lsum1, g4, c4);

    // lsum: reduce across c4 lanes (warp owns all keys for its rows)
    lsum0 += __shfl_xor_sync(0xffffffffu, lsum0, 1);
    lsum0 += __shfl_xor_sync(0xffffffffu, lsum0, 2);
    lsum1 += __shfl_xor_sync(0xffffffffu, lsum1, 1);
    lsum1 += __shfl_xor_sync(0xffffffffu, lsum1, 2);
    const float inv0 = 1.f / lsum0;
    const float inv1 = 1.f / lsum1;

    // epilogue: warp writes its 16 rows x 128 d
    {
        float* op0 = out + ((size_t)b*SS + qt*64 + wid*16 + g4)*1024 + h*128 + 2*c4;
        float* op1 = op0 + 8*1024;
        #pragma unroll
        for (int nt = 0; nt < 16; ++nt) {
            *reinterpret_cast<float2*>(op0 + nt*8) =
                make_float2(O[nt][0]*inv0, O[nt][1]*inv0);
            *reinterpret_cast<float2*>(op1 + nt*8) =
                make_float2(O[nt][2]*inv1, O[nt][3]*inv1);
        }
    }
}

// ---------------------------------------------------------------------------
extern "C" void kernel_launch(void* const* d_in, const int* in_sizes, int n_in,
                              void* d_out, int out_size) {
    (void)in_sizes; (void)n_in; (void)out_size;
    const float* x  = (const float*)d_in[0];
    const float* Uq = (const float*)d_in[1];
    const float* Vq = (const float*)d_in[2];
    const float* bq = (const float*)d_in[3];
    const float* Uk = (const float*)d_in[4];
    const float* Vk = (const float*)d_in[5];
    const float* bk = (const float*)d_in[6];
    const float* Uv = (const float*)d_in[7];
    const float* Vv = (const float*)d_in[8];
    const float* bv = (const float*)d_in[9];
    float* out = (float*)d_out;

    const int qkv_smem  = QJ_FLTS * 4;   // 104960 B -> 2 CTAs/SM
    const int attn_smem = AT_U32 * 4;    // 55296 B  -> 4 CTAs/SM
    cudaFuncSetAttribute(qkv_kernel,
                         cudaFuncAttributeMaxDynamicSharedMemorySize, qkv_smem);
    cudaFuncSetAttribute(attn_kernel,
                         cudaFuncAttributeMaxDynamicSharedMemorySize, attn_smem);

    qkv_kernel<<<dim3(SS/128, HH*3, BB), 256, qkv_smem>>>(x, Uq, Vq, bq, Uk, Vk, bk, Uv, Vv, bv);
    attn_kernel<<<dim3(SS/64, HH, BB), 128, attn_smem>>>(out);
}

// round 17
// speedup vs baseline: 1.0702x; 1.0472x over previous
#include <cuda_runtime.h>
#include <cstdint>

#define BB 8
#define SS 1024
#define HH 8
#define DHD 128

// bf16x2-packed scratch, fragment-permuted layouts:
// g_Qb/g_Kb: [b][h][s][64 u32]  (d pairs, per-16 block permuted)
// g_Vtb:     [b][h][d][512 u32] (s pairs, per-16 block permuted)
__device__ uint32_t g_Qb [BB*HH*SS*64];
__device__ uint32_t g_Kb [BB*HH*SS*64];
__device__ uint32_t g_Vtb[BB*HH*DHD*512];

__device__ __forceinline__ uint32_t packbf(float lo, float hi) {
    uint32_t r;
    asm("cvt.rn.bf16x2.f32 %0, %1, %2;" : "=r"(r) : "f"(hi), "f"(lo));
    return r;
}
__device__ __forceinline__ float ex2f(float x) {
    float r;
    asm("ex2.approx.f32 %0, %1;" : "=f"(r) : "f"(x));
    return r;
}
__device__ __forceinline__ uint32_t smem_u32(const void* p) {
    uint32_t a;
    asm("{ .reg .u64 t; cvta.to.shared.u64 t, %1; cvt.u32.u64 %0, t; }" : "=r"(a) : "l"(p));
    return a;
}
// tf32 m16n8k8: operands are raw fp32 bits (HW truncates low mantissa).
__device__ __forceinline__ void mma8(float* d, const uint32_t* a, const uint32_t* b) {
    asm volatile("mma.sync.aligned.m16n8k8.row.col.f32.tf32.tf32.f32 "
        "{%0,%1,%2,%3}, {%4,%5,%6,%7}, {%8,%9}, {%0,%1,%2,%3};"
        : "+f"(d[0]), "+f"(d[1]), "+f"(d[2]), "+f"(d[3])
        : "r"(a[0]), "r"(a[1]), "r"(a[2]), "r"(a[3]), "r"(b[0]), "r"(b[1]));
}
__device__ __forceinline__ void mma16(float* d, const uint32_t* a, uint32_t b0, uint32_t b1) {
    asm volatile("mma.sync.aligned.m16n8k16.row.col.f32.bf16.bf16.f32 "
        "{%0,%1,%2,%3}, {%4,%5,%6,%7}, {%8,%9}, {%0,%1,%2,%3};"
        : "+f"(d[0]), "+f"(d[1]), "+f"(d[2]), "+f"(d[3])
        : "r"(a[0]), "r"(a[1]), "r"(a[2]), "r"(a[3]), "r"(b0), "r"(b1));
}
#define CP_ASYNC16(dst, src) \
    asm volatile("cp.async.cg.shared.global [%0], [%1], 16;" :: "r"(dst), "l"(src) : "memory")
#define CP_COMMIT() asm volatile("cp.async.commit_group;" ::: "memory")
#define CP_WAIT(n)  asm volatile("cp.async.wait_group %0;" :: "n"(n) : "memory")

// ---------------------------------------------------------------------------
// Kernel 1 (exact R14): low-rank projection, ONE projection per 128-row CTA
// (p fastest in y for x-slice L2 reuse), 256 threads, 2 CTAs/SM.
// Two cp.async groups: (WV+X) before stage A, (WU+bias) before stage B.
// SMEM floats: Xs[128*132]@0 | WV/T[4608]@16896 | WU[4608]@21504 | b[128]@26112
// ---------------------------------------------------------------------------
#define QJ_XS   0
#define QJ_WV   16896
#define QJ_WU   21504
#define QJ_B    26112
#define QJ_FLTS 26240

__global__ __launch_bounds__(256, 2) void qkv_kernel(
    const float* __restrict__ x,
    const float* __restrict__ Uq, const float* __restrict__ Vq, const float* __restrict__ bq,
    const float* __restrict__ Uk, const float* __restrict__ Vk, const float* __restrict__ bk,
    const float* __restrict__ Uv, const float* __restrict__ Vv, const float* __restrict__ bv)
{
    extern __shared__ __align__(16) float sm[];
    float* Xs = sm + QJ_XS;
    uint32_t* Xsu = reinterpret_cast<uint32_t*>(Xs);
    uint32_t* Vwu = reinterpret_cast<uint32_t*>(sm + QJ_WV);
    uint32_t* Tsu = Vwu;                       // T aliases WV after stage A
    float*    Tsf = reinterpret_cast<float*>(Tsu);
    uint32_t* Uwu = reinterpret_cast<uint32_t*>(sm + QJ_WU);
    const float* bsm = sm + QJ_B;

    const uint32_t sb = smem_u32(sm);
    const int tid  = threadIdx.x;
    const int wid  = tid >> 5;
    const int lane = tid & 31;
    const int g4   = lane >> 2;
    const int c4   = lane & 3;

    const int s0 = blockIdx.x * 128;
    const int h  = blockIdx.y / 3;
    const int p  = blockIdx.y - h*3;
    const int b  = blockIdx.z;
    const size_t bh = (size_t)(b*HH + h);

    const float* Ug = (p == 0) ? Uq : (p == 1) ? Uk : Uv;
    const float* Vg = (p == 0) ? Vq : (p == 1) ? Vk : Vv;
    const float* bg = (p == 0) ? bq : (p == 1) ? bk : bv;

    // group 0: WV + X  (everything stage A needs)
    {
        const float4* vg = reinterpret_cast<const float4*>(Vg) + h*1024;
        #pragma unroll
        for (int k = 0; k < 4; ++k) {
            int idx = tid + (k << 8);
            int r = idx >> 5, dq = idx & 31;
            CP_ASYNC16(sb + (QJ_WV + (r*33 + dq)*4)*4, vg + r*32 + dq);
        }
        const float4* xg = reinterpret_cast<const float4*>(x);
        #pragma unroll
        for (int k = 0; k < 16; ++k) {
            int idx = tid + (k << 8);
            int r = idx >> 5, dq = idx & 31;
            CP_ASYNC16(sb + (QJ_XS + (r*132 + dq*4))*4,
                       xg + (size_t)(b*SS + s0 + r)*256 + h*32 + dq);
        }
        CP_COMMIT();
    }
    // group 1: WU + bias (needed only by stage B)
    {
        const float4* ug = reinterpret_cast<const float4*>(Ug) + h*1024;
        #pragma unroll
        for (int k = 0; k < 4; ++k) {
            int idx = tid + (k << 8);
            int dI = idx >> 3, rr = idx & 7;
            CP_ASYNC16(sb + (QJ_WU + (dI*9 + rr)*4)*4, ug + dI*8 + rr);
        }
        if (tid < 32)
            CP_ASYNC16(sb + (QJ_B + tid*4)*4,
                       reinterpret_cast<const float4*>(bg) + h*32 + tid);
        CP_COMMIT();
    }

    CP_WAIT(1);
    __syncthreads();

    // ---- stage A: T[128,32], warp = 16 rows x 32 cols ----
    const int r0 = wid*16 + g4;
    float Tacc[4][4];
    #pragma unroll
    for (int nt = 0; nt < 4; ++nt)
        #pragma unroll
        for (int e = 0; e < 4; ++e) Tacc[nt][e] = 0.f;

    #pragma unroll
    for (int ks = 0; ks < 16; ++ks) {
        int kc = ks*8 + c4;
        uint32_t a[4];
        a[0] = Xsu[r0*132 + kc];
        a[1] = Xsu[(r0+8)*132 + kc];
        a[2] = Xsu[r0*132 + kc + 4];
        a[3] = Xsu[(r0+8)*132 + kc + 4];
        #pragma unroll
        for (int nt = 0; nt < 4; ++nt) {
            int n = nt*8 + g4;
            uint32_t bfr[2] = { Vwu[n*132 + kc], Vwu[n*132 + kc + 4] };
            mma8(Tacc[nt], a, bfr);
        }
    }
    __syncthreads();   // all stage-A reads of WV done before T overwrites it

    // write T (raw fp32; tf32 truncation happens inside the MMA)
    #pragma unroll
    for (int nt = 0; nt < 4; ++nt) {
        int c = nt*8 + 2*c4;
        *reinterpret_cast<float2*>(&Tsf[r0*36 + c]) =
            make_float2(Tacc[nt][0], Tacc[nt][1]);
        *reinterpret_cast<float2*>(&Tsf[(r0+8)*36 + c]) =
            make_float2(Tacc[nt][2], Tacc[nt][3]);
    }
    CP_WAIT(0);
    __syncthreads();

    // ---- stage B: Y[128,128] = T @ Uw^T, warp grid 4x2 ----
    const int wr = wid >> 1, wc = wid & 1;
    const int rb = wr*32 + g4;
    float Y[2][8][4];
    #pragma unroll
    for (int mt = 0; mt < 2; ++mt)
        #pragma unroll
        for (int nt = 0; nt < 8; ++nt)
            #pragma unroll
            for (int e = 0; e < 4; ++e) Y[mt][nt][e] = 0.f;

    #pragma unroll
    for (int ks2 = 0; ks2 < 4; ++ks2) {
        int kk = ks2*8 + c4;
        uint32_t a[2][4];
        #pragma unroll
        for (int mt = 0; mt < 2; ++mt) {
            int r = rb + mt*16;
            a[mt][0] = Tsu[r*36 + kk];
            a[mt][1] = Tsu[(r+8)*36 + kk];
            a[mt][2] = Tsu[r*36 + kk + 4];
            a[mt][3] = Tsu[(r+8)*36 + kk + 4];
        }
        #pragma unroll
        for (int nt = 0; nt < 8; ++nt) {
            int n = wc*64 + nt*8 + g4;
            uint32_t bfr[2] = { Uwu[n*36 + kk], Uwu[n*36 + kk + 4] };
            mma8(Y[0][nt], a[0], bfr);
            mma8(Y[1][nt], a[1], bfr);
        }
    }

    if (p < 2) {
        const float scl = (p == 0) ? 0.12751744610657804f : 1.0f;
        uint32_t* og = (p == 0 ? g_Qb : g_Kb) + (bh*SS + s0)*64;
        #pragma unroll
        for (int mt = 0; mt < 2; ++mt) {
            int r = rb + mt*16;
            #pragma unroll
            for (int nt = 0; nt < 8; ++nt) {
                int c = wc*64 + nt*8 + 2*c4;
                int ks = wc*4 + (nt >> 1);
                int dest = (ks >> 1)*16 + c4*4 + (ks & 1)*2 + (nt & 1);
                float bv0 = bsm[c], bv1 = bsm[c+1];
                og[(size_t)r*64 + dest] =
                    packbf((Y[mt][nt][0]+bv0)*scl, (Y[mt][nt][1]+bv1)*scl);
                og[(size_t)(r+8)*64 + dest] =
                    packbf((Y[mt][nt][2]+bv0)*scl, (Y[mt][nt][3]+bv1)*scl);
            }
        }
    } else {
        // V: transpose via Xs (X is dead), then permuted bf16x2 store
        __syncthreads();
        #pragma unroll
        for (int mt = 0; mt < 2; ++mt) {
            int r = rb + mt*16;
            #pragma unroll
            for (int nt = 0; nt < 8; ++nt) {
                int c = wc*64 + nt*8 + 2*c4;
                float bv0 = bsm[c], bv1 = bsm[c+1];
                Xs[c*132 + r]         = Y[mt][nt][0]+bv0;
                Xs[(c+1)*132 + r]     = Y[mt][nt][1]+bv1;
                Xs[c*132 + r + 8]     = Y[mt][nt][2]+bv0;
                Xs[(c+1)*132 + r + 8] = Y[mt][nt][3]+bv1;
            }
        }
        __syncthreads();
        uint32_t* vt = g_Vtb + bh*DHD*512;
        #pragma unroll
        for (int k = 0; k < 32; ++k) {
            int idx = tid + (k << 8);
            int d = idx >> 6, gp = idx & 63;
            float v0 = Xs[d*132 + 2*gp];
            float v1 = Xs[d*132 + 2*gp + 1];
            int tile = gp >> 4, j = gp & 15;
            int s = j & 7, ks2 = j >> 3;
            int dest = (s & 3)*4 + ks2*2 + (s >> 2);
            vt[(size_t)d*512 + blockIdx.x*64 + tile*16 + dest] = packbf(v0, v1);
        }
    }
}

// ---------------------------------------------------------------------------
// Kernel 2: flash attention (R14 structure; ONLY change: wrap-around buffer
// counters replace i/3-based indexing — +2 regs of state, same code size).
// bf16 m16n8k16, warp-local P, 64-row CTAs, 128 threads, 4 CTAs/SM,
// 3 KV buffers, depth-2 prefetch, wait(1) invariant.
// SMEM u32: K[3][2560]@0 | V[3][2048]@7680   (55296 B -> 4 CTAs/SM)
// ---------------------------------------------------------------------------
#define K_STRIDE 2560
#define V_BASE   7680
#define V_STRIDE 2048
#define AT_U32   13824

__global__ __launch_bounds__(128, 4) void attn_kernel(float* __restrict__ out)
{
    extern __shared__ __align__(16) uint32_t smu[];
    const uint32_t sb = smem_u32(smu);

    const int tid  = threadIdx.x;
    const int wid  = tid >> 5;
    const int lane = tid & 31;
    const int g4   = lane >> 2;
    const int c4   = lane & 3;

    const int qt = blockIdx.x;           // 64-row tile
    const int h  = blockIdx.y;
    const int b  = blockIdx.z;
    const size_t bh = (size_t)(b*HH + h);

    const uint32_t* Kg = g_Kb + bh*SS*64;
    const uint32_t* Vg = g_Vtb + bh*DHD*512;

    // prefetch tiles 0,1 (one commit group per tile)
    #pragma unroll
    for (int t = 0; t < 2; ++t) {
        #pragma unroll
        for (int k = 0; k < 4; ++k) {
            int idx = tid + (k << 7);
            int r = idx >> 4, ch = idx & 15;
            CP_ASYNC16(sb + (t*K_STRIDE + r*80 + ch*4)*4, Kg + (t*32 + r)*64 + ch*4);
        }
        #pragma unroll
        for (int k = 0; k < 4; ++k) {
            int idx = tid + (k << 7);
            int r = idx >> 2, ch = idx & 3;
            CP_ASYNC16(sb + (V_BASE + t*V_STRIDE + r*16 + ch*4)*4,
                       Vg + (size_t)r*512 + t*16 + ch*4);
        }
        CP_COMMIT();
    }

    // Q fragments in registers (rows qt*64 + wid*16 + g4 / +8)
    uint32_t qa[8][4];
    {
        const uint32_t* q0 = g_Qb + (bh*SS + (size_t)qt*64 + wid*16 + g4)*64;
        #pragma unroll
        for (int ks = 0; ks < 8; ++ks) {
            int col = (ks >> 1)*16 + c4*4 + (ks & 1)*2;
            uint2 lo = *reinterpret_cast<const uint2*>(q0 + col);
            uint2 hi = *reinterpret_cast<const uint2*>(q0 + 8*64 + col);
            qa[ks][0] = lo.x; qa[ks][2] = lo.y;
            qa[ks][1] = hi.x; qa[ks][3] = hi.y;
        }
    }

    float O[16][4];
    #pragma unroll
    for (int nt = 0; nt < 16; ++nt)
        #pragma unroll
        for (int e = 0; e < 4; ++e) O[nt][e] = 0.f;
    float lsum0 = 0.f, lsum1 = 0.f;

    int cbuf = 0;   // buffer holding tile i
    int pbuf = 2;   // buffer receiving tile i+2

    #pragma unroll 1
    for (int i = 0; i < 32; ++i) {
        if (i < 31) { CP_WAIT(1); } else { CP_WAIT(0); }
        __syncthreads();

        // prefetch tile i+2 into buf pbuf (last read at tile i-1; barrier-safe)
        if (i < 30) {
            int t = i + 2;
            #pragma unroll
            for (int k = 0; k < 4; ++k) {
                int idx = tid + (k << 7);
                int r = idx >> 4, ch = idx & 15;
                CP_ASYNC16(sb + (pbuf*K_STRIDE + r*80 + ch*4)*4,
                           Kg + ((size_t)t*32 + r)*64 + ch*4);
            }
            #pragma unroll
            for (int k = 0; k < 4; ++k) {
                int idx = tid + (k << 7);
                int r = idx >> 2, ch = idx & 3;
                CP_ASYNC16(sb + (V_BASE + pbuf*V_STRIDE + r*16 + ch*4)*4,
                           Vg + (size_t)r*512 + t*16 + ch*4);
            }
            CP_COMMIT();
        }
        pbuf = (pbuf == 2) ? 0 : pbuf + 1;

        const uint32_t* Ks = smu + cbuf*K_STRIDE;
        const uint32_t* Vs = smu + V_BASE + cbuf*V_STRIDE;
        cbuf = (cbuf == 2) ? 0 : cbuf + 1;

        // ---- S = Q K^T over 32 keys ----
        float S[4][4];
        #pragma unroll
        for (int nt = 0; nt < 4; ++nt) {
            #pragma unroll
            for (int e = 0; e < 4; ++e) S[nt][e] = 0.f;
            const uint32_t* krow = Ks + (nt*8 + g4)*80 + c4*4;
            #pragma unroll
            for (int w = 0; w < 4; ++w) {
                uint4 kv = *reinterpret_cast<const uint4*>(krow + w*16);
                mma16(S[nt], qa[2*w],     kv.x, kv.y);
                mma16(S[nt], qa[2*w + 1], kv.z, kv.w);
            }
        }

        // ---- P = ex2(S) in registers; repack C->A (bf16) ----
        uint32_t ap[2][4];
        #pragma unroll
        for (int nt = 0; nt < 4; ++nt) {
            float p0 = ex2f(S[nt][0]);
            float p1 = ex2f(S[nt][1]);
            float p2 = ex2f(S[nt][2]);
            float p3 = ex2f(S[nt][3]);
            lsum0 += p0 + p1;
            lsum1 += p2 + p3;
            ap[nt >> 1][(nt & 1) ? 2 : 0] = packbf(p0, p1);
            ap[nt >> 1][(nt & 1) ? 3 : 1] = packbf(p2, p3);
        }

        // ---- O += P V over all 128 d ----
        #pragma unroll
        for (int nt = 0; nt < 16; ++nt) {
            uint4 vv = *reinterpret_cast<const uint4*>(Vs + (nt*8 + g4)*16 + c4*4);
            mma16(O[nt], ap[0], vv.x, vv.y);
            mma16(O[nt], ap[1], vv.z, vv.w);
        }
    }

    // lsum: reduce across c4 lanes (warp owns all keys for its rows)
    lsum0 += __shfl_xor_sync(0xffffffffu, lsum0, 1);
    lsum0 += __shfl_xor_sync(0xffffffffu, lsum0, 2);
    lsum1 += __shfl_xor_sync(0xffffffffu, lsum1, 1);
    lsum1 += __shfl_xor_sync(0xffffffffu, lsum1, 2);
    const float inv0 = 1.f / lsum0;
    const float inv1 = 1.f / lsum1;

    // epilogue: warp writes its 16 rows x 128 d
    {
        float* op0 = out + ((size_t)b*SS + qt*64 + wid*16 + g4)*1024 + h*128 + 2*c4;
        float* op1 = op0 + 8*1024;
        #pragma unroll
        for (int nt = 0; nt < 16; ++nt) {
            *reinterpret_cast<float2*>(op0 + nt*8) =
                make_float2(O[nt][0]*inv0, O[nt][1]*inv0);
            *reinterpret_cast<float2*>(op1 + nt*8) =
                make_float2(O[nt][2]*inv1, O[nt][3]*inv1);
        }
    }
}

// ---------------------------------------------------------------------------
extern "C" void kernel_launch(void* const* d_in, const int* in_sizes, int n_in,
                              void* d_out, int out_size) {
    (void)in_sizes; (void)n_in; (void)out_size;
    const float* x  = (const float*)d_in[0];
    const float* Uq = (const float*)d_in[1];
    const float* Vq = (const float*)d_in[2];
    const float* bq = (const float*)d_in[3];
    const float* Uk = (const float*)d_in[4];
    const float* Vk = (const float*)d_in[5];
    const float* bk = (const float*)d_in[6];
    const float* Uv = (const float*)d_in[7];
    const float* Vv = (const float*)d_in[8];
    const float* bv = (const float*)d_in[9];
    float* out = (float*)d_out;

    const int qkv_smem  = QJ_FLTS * 4;   // 104960 B -> 2 CTAs/SM
    const int attn_smem = AT_U32 * 4;    // 55296 B  -> 4 CTAs/SM
    cudaFuncSetAttribute(qkv_kernel,
                         cudaFuncAttributeMaxDynamicSharedMemorySize, qkv_smem);
    cudaFuncSetAttribute(attn_kernel,
                         cudaFuncAttributeMaxDynamicSharedMemorySize, attn_smem);

    qkv_kernel<<<dim3(SS/128, HH*3, BB), 256, qkv_smem>>>(x, Uq, Vq, bq, Uk, Vk, bk, Uv, Vv, bv);
    attn_kernel<<<dim3(SS/64, HH, BB), 128, attn_smem>>>(out);
}